// round 8
// baseline (speedup 1.0000x reference)
#include <cuda_runtime.h>
#include <cstdint>

#define N_NODES 50000
#define N_EDGES 800000
#define D 128
#define BN_EPS 1e-5f

// ---------------- scratch (no allocations allowed) ----------------
__device__ double g_sum[D];
__device__ double g_sumsq[D];
__device__ float  g_scale[D];
__device__ float  g_bias[D];
__device__ unsigned g_done;
__device__ int g_count[N_NODES];
__device__ int g_off[N_NODES + 1];
__device__ int g_cursor[N_NODES];
__device__ int g_csr[N_EDGES];

// ---------------- K1: zero counters + stats ----------------
__global__ void __launch_bounds__(256) k_zero() {
    int i = blockIdx.x * blockDim.x + threadIdx.x;
    if (i < D) { g_sum[i] = 0.0; g_sumsq[i] = 0.0; }
    if (i == 0) g_done = 0;
    if (i < N_NODES) g_count[i] = 0;
}

// ---------------- K2: dst histogram (4 edges/thread) ----------------
__global__ void __launch_bounds__(256) k_hist(const int* __restrict__ dst) {
    int t = blockIdx.x * blockDim.x + threadIdx.x;
    if (t >= N_EDGES / 4) return;
    int4 d4 = ((const int4*)dst)[t];
    atomicAdd(&g_count[d4.x], 1);
    atomicAdd(&g_count[d4.y], 1);
    atomicAdd(&g_count[d4.z], 1);
    atomicAdd(&g_count[d4.w], 1);
}

// ---------------- K3: exclusive scan (1 block) ----------------
#define SCAN_THREADS 1024
#define SCAN_ITEMS ((N_NODES + SCAN_THREADS - 1) / SCAN_THREADS)   // 49
__global__ void __launch_bounds__(SCAN_THREADS) k_scan() {
    __shared__ int s_part[SCAN_THREADS];
    int t = threadIdx.x;
    int begin = t * SCAN_ITEMS;
    int end = begin + SCAN_ITEMS; if (end > N_NODES) end = N_NODES;

    int sum = 0;
#pragma unroll 8
    for (int i = begin; i < end; i++) sum += g_count[i];
    s_part[t] = sum;
    __syncthreads();
    for (int off = 1; off < SCAN_THREADS; off <<= 1) {
        int v = (t >= off) ? s_part[t - off] : 0;
        __syncthreads();
        s_part[t] += v;
        __syncthreads();
    }
    int run = (t == 0) ? 0 : s_part[t - 1];
#pragma unroll 8
    for (int i = begin; i < end; i++) {
        int c = g_count[i];
        g_off[i] = run;
        g_cursor[i] = run;
        run += c;
    }
    if (t == SCAN_THREADS - 1) g_off[N_NODES] = N_EDGES;
}

// ---------------- K4: CSR fill (4 edges/thread) ----------------
__global__ void __launch_bounds__(256) k_fill(
    const int* __restrict__ src, const int* __restrict__ dst)
{
    int t = blockIdx.x * blockDim.x + threadIdx.x;
    if (t >= N_EDGES / 4) return;
    int4 d4 = ((const int4*)dst)[t];
    int4 s4 = ((const int4*)src)[t];
    int p0 = atomicAdd(&g_cursor[d4.x], 1);
    int p1 = atomicAdd(&g_cursor[d4.y], 1);
    int p2 = atomicAdd(&g_cursor[d4.z], 1);
    int p3 = atomicAdd(&g_cursor[d4.w], 1);
    g_csr[p0] = s4.x;
    g_csr[p1] = s4.y;
    g_csr[p2] = s4.z;
    g_csr[p3] = s4.w;
}

// ---------------- K5: fused gather + combine + stats + finalize ----------------
// warp per dst row; lane owns channels [lane*4, lane*4+4); inner loop 4-way MLP
#define GATHER_BLOCKS 1184
__global__ void __launch_bounds__(256) k_gather(
    const float* __restrict__ h, const float* __restrict__ norm,
    const float* __restrict__ eps_p,
    const float* __restrict__ gamma, const float* __restrict__ beta,
    float* __restrict__ out)
{
    int lane = threadIdx.x & 31;
    int wid  = threadIdx.x >> 5;
    int gw   = blockIdx.x * 8 + wid;
    int nw   = GATHER_BLOCKS * 8;
    float epsv = 1.0f + eps_p[0];

    float4 lsum = make_float4(0.f, 0.f, 0.f, 0.f);
    float4 lsq  = make_float4(0.f, 0.f, 0.f, 0.f);

    for (int r = gw; r < N_NODES; r += nw) {
        int base = __ldg(g_off + r);
        int end  = __ldg(g_off + r + 1);
        float nd = __ldg(norm + r);

        float4 acc = make_float4(0.f, 0.f, 0.f, 0.f);
        int i = base;
        // 4-way batched loads: 4 independent h-row gathers in flight
        for (; i + 4 <= end; i += 4) {
            int s0 = __ldg(g_csr + i + 0);
            int s1 = __ldg(g_csr + i + 1);
            int s2 = __ldg(g_csr + i + 2);
            int s3 = __ldg(g_csr + i + 3);
            float w0 = __ldg(norm + s0);
            float w1 = __ldg(norm + s1);
            float w2 = __ldg(norm + s2);
            float w3 = __ldg(norm + s3);
            float4 a0 = __ldg((const float4*)(h + (size_t)s0 * D) + lane);
            float4 a1 = __ldg((const float4*)(h + (size_t)s1 * D) + lane);
            float4 a2 = __ldg((const float4*)(h + (size_t)s2 * D) + lane);
            float4 a3 = __ldg((const float4*)(h + (size_t)s3 * D) + lane);
            acc.x = fmaf(a0.x, w0, acc.x); acc.y = fmaf(a0.y, w0, acc.y);
            acc.z = fmaf(a0.z, w0, acc.z); acc.w = fmaf(a0.w, w0, acc.w);
            acc.x = fmaf(a1.x, w1, acc.x); acc.y = fmaf(a1.y, w1, acc.y);
            acc.z = fmaf(a1.z, w1, acc.z); acc.w = fmaf(a1.w, w1, acc.w);
            acc.x = fmaf(a2.x, w2, acc.x); acc.y = fmaf(a2.y, w2, acc.y);
            acc.z = fmaf(a2.z, w2, acc.z); acc.w = fmaf(a2.w, w2, acc.w);
            acc.x = fmaf(a3.x, w3, acc.x); acc.y = fmaf(a3.y, w3, acc.y);
            acc.z = fmaf(a3.z, w3, acc.z); acc.w = fmaf(a3.w, w3, acc.w);
        }
        for (; i < end; i++) {
            int s = __ldg(g_csr + i);
            float ws = __ldg(norm + s);
            float4 hv = __ldg((const float4*)(h + (size_t)s * D) + lane);
            acc.x = fmaf(hv.x, ws, acc.x);
            acc.y = fmaf(hv.y, ws, acc.y);
            acc.z = fmaf(hv.z, ws, acc.z);
            acc.w = fmaf(hv.w, ws, acc.w);
        }

        float4 hs = __ldg((const float4*)(h + (size_t)r * D) + lane);
        float a = epsv * nd * nd;
        float4 v;
        v.x = fmaf(hs.x, a, acc.x * nd);
        v.y = fmaf(hs.y, a, acc.y * nd);
        v.z = fmaf(hs.z, a, acc.z * nd);
        v.w = fmaf(hs.w, a, acc.w * nd);
        ((float4*)(out + (size_t)r * D))[lane] = v;

        lsum.x += v.x; lsum.y += v.y; lsum.z += v.z; lsum.w += v.w;
        lsq.x  = fmaf(v.x, v.x, lsq.x);
        lsq.y  = fmaf(v.y, v.y, lsq.y);
        lsq.z  = fmaf(v.z, v.z, lsq.z);
        lsq.w  = fmaf(v.w, v.w, lsq.w);
    }

    // block-level stats reduction: 8 warps x 128 channels
    __shared__ float s_sum[8][D];
    __shared__ float s_sq[8][D];
    int c0 = lane * 4;
    s_sum[wid][c0 + 0] = lsum.x; s_sum[wid][c0 + 1] = lsum.y;
    s_sum[wid][c0 + 2] = lsum.z; s_sum[wid][c0 + 3] = lsum.w;
    s_sq[wid][c0 + 0]  = lsq.x;  s_sq[wid][c0 + 1]  = lsq.y;
    s_sq[wid][c0 + 2]  = lsq.z;  s_sq[wid][c0 + 3]  = lsq.w;
    __syncthreads();

    int c = threadIdx.x;
    if (c < D) {
        float ts = 0.f, tq = 0.f;
#pragma unroll
        for (int w2 = 0; w2 < 8; w2++) { ts += s_sum[w2][c]; tq += s_sq[w2][c]; }
        atomicAdd(&g_sum[c],   (double)ts);
        atomicAdd(&g_sumsq[c], (double)tq);
    }

    // last block finalizes scale/bias
    __threadfence();
    __syncthreads();
    __shared__ int s_last;
    if (threadIdx.x == 0)
        s_last = (atomicAdd(&g_done, 1u) == (unsigned)(GATHER_BLOCKS - 1));
    __syncthreads();
    if (s_last && c < D) {
        double su  = __ldcg(&g_sum[c]);
        double ssq = __ldcg(&g_sumsq[c]);
        double mu  = su / (double)N_NODES;
        double var = ssq / (double)N_NODES - mu * mu;
        double rstd = 1.0 / sqrt(var + (double)BN_EPS);
        float sc = gamma[c] * (float)rstd;
        g_scale[c] = sc;
        g_bias[c]  = beta[c] - (float)mu * sc;
    }
}

// ---------------- K6: BN apply + ReLU ----------------
__global__ void __launch_bounds__(256) k_bn(float* __restrict__ out)
{
    __shared__ float4 s_scale4[D / 4];
    __shared__ float4 s_bias4[D / 4];

    int tid = threadIdx.x;
    if (tid < D) {
        ((float*)s_scale4)[tid] = g_scale[tid];
        ((float*)s_bias4)[tid]  = g_bias[tid];
    }
    __syncthreads();

    int i4 = blockIdx.x * blockDim.x + tid;
    if (i4 >= (N_NODES * D) / 4) return;
    int c4 = i4 & (D / 4 - 1);
    float4 sc = s_scale4[c4];
    float4 bi = s_bias4[c4];
    float4 x = ((float4*)out)[i4];
    x.x = fmaxf(fmaf(x.x, sc.x, bi.x), 0.f);
    x.y = fmaxf(fmaf(x.y, sc.y, bi.y), 0.f);
    x.z = fmaxf(fmaf(x.z, sc.z, bi.z), 0.f);
    x.w = fmaxf(fmaf(x.w, sc.w, bi.w), 0.f);
    ((float4*)out)[i4] = x;
}

// ---------------- launch ----------------
extern "C" void kernel_launch(void* const* d_in, const int* in_sizes, int n_in,
                              void* d_out, int out_size)
{
    const float* h     = (const float*)d_in[0];
    const float* norm  = (const float*)d_in[1];
    const float* eps   = (const float*)d_in[2];
    const float* gamma = (const float*)d_in[3];
    const float* beta  = (const float*)d_in[4];
    const int*   src   = (const int*)d_in[5];
    const int*   dst   = (const int*)d_in[6];
    float* out = (float*)d_out;

    (void)in_sizes; (void)n_in; (void)out_size;

    k_zero<<<(N_NODES + 255) / 256, 256>>>();
    k_hist<<<(N_EDGES / 4 + 255) / 256, 256>>>(dst);
    k_scan<<<1, SCAN_THREADS>>>();
    k_fill<<<(N_EDGES / 4 + 255) / 256, 256>>>(src, dst);
    k_gather<<<GATHER_BLOCKS, 256>>>(h, norm, eps, gamma, beta, out);

    const int total4 = (N_NODES * D) / 4;
    k_bn<<<(total4 + 255) / 256, 256>>>(out);
}

// round 9
// speedup vs baseline: 1.4937x; 1.4937x over previous
#include <cuda_runtime.h>
#include <cstdint>

#define N_NODES 50000
#define N_EDGES 800000
#define D 128
#define BN_EPS 1e-5f

// ---------------- scratch (no allocations allowed) ----------------
__device__ double g_sum[D];
__device__ double g_sumsq[D];
__device__ float  g_scale[D];
__device__ float  g_bias[D];
__device__ unsigned g_done;

// ---------------- K1: init out = (1+eps)*h*norm^2, zero stats ----------------
__global__ void __launch_bounds__(256) k_init(
    const float* __restrict__ h, const float* __restrict__ norm,
    const float* __restrict__ eps_p, float* __restrict__ out)
{
    int i4 = blockIdx.x * blockDim.x + threadIdx.x;
    if (i4 < D) { g_sum[i4] = 0.0; g_sumsq[i4] = 0.0; }
    if (i4 == 0) g_done = 0;
    if (i4 >= (N_NODES * D) / 4) return;
    int row = i4 >> 5;                       // D/4 = 32 float4 per row
    float n = norm[row];
    float s = (1.0f + eps_p[0]) * n * n;
    float4 hv = ((const float4*)h)[i4];
    ((float4*)out)[i4] = make_float4(hv.x * s, hv.y * s, hv.z * s, hv.w * s);
}

// ---------------- K2: edge scatter (2 edges per warp) ----------------
// lane l handles float4 chunk l of both edges; two independent gather+red chains.
__global__ void __launch_bounds__(256) k_edges(
    const float* __restrict__ h, const float* __restrict__ norm,
    const int* __restrict__ src, const int* __restrict__ dst,
    float* __restrict__ out)
{
    long long t = (long long)blockIdx.x * blockDim.x + threadIdx.x;
    int w    = (int)(t >> 5);            // warp id = edge pair id
    int lane = (int)(t & 31);
    if (2 * w >= N_EDGES) return;

    int2 s2 = __ldg((const int2*)src + w);   // warp-uniform
    int2 d2 = __ldg((const int2*)dst + w);   // warp-uniform
    float w0 = __ldg(norm + s2.x) * __ldg(norm + d2.x);
    float w1 = __ldg(norm + s2.y) * __ldg(norm + d2.y);

    float4 a = __ldg((const float4*)(h + (size_t)s2.x * D) + lane);
    float4 b = __ldg((const float4*)(h + (size_t)s2.y * D) + lane);

    float4 va = make_float4(a.x * w0, a.y * w0, a.z * w0, a.w * w0);
    float4 vb = make_float4(b.x * w1, b.y * w1, b.z * w1, b.w * w1);

    float* p0 = out + (size_t)d2.x * D + lane * 4;
    float* p1 = out + (size_t)d2.y * D + lane * 4;
    asm volatile("red.global.add.v4.f32 [%0], {%1,%2,%3,%4};"
                 :: "l"(p0), "f"(va.x), "f"(va.y), "f"(va.z), "f"(va.w)
                 : "memory");
    asm volatile("red.global.add.v4.f32 [%0], {%1,%2,%3,%4};"
                 :: "l"(p1), "f"(vb.x), "f"(vb.y), "f"(vb.z), "f"(vb.w)
                 : "memory");
}

// ---------------- K3: read-only stats (256 thr) + last-block finalize ----------------
#define SROWS 64                         // rows per block (split across 2 half-blocks)
__global__ void __launch_bounds__(256) k_stats_partial(
    const float* __restrict__ gamma, const float* __restrict__ beta,
    const float* __restrict__ out, int nblocks)
{
    int c    = threadIdx.x & 127;        // channel
    int half = threadIdx.x >> 7;         // 0 or 1
    int row0 = blockIdx.x * SROWS + half * (SROWS / 2);

    float lsum = 0.f, lsq = 0.f;
#pragma unroll 8
    for (int r = 0; r < SROWS / 2; r++) {
        int row = row0 + r;
        if (row >= N_NODES) break;
        float v = __ldg(out + (size_t)row * D + c);
        lsum += v;
        lsq  += v * v;
    }

    __shared__ float s_s[2][D];
    __shared__ float s_q[2][D];
    s_s[half][c] = lsum;
    s_q[half][c] = lsq;
    __syncthreads();

    if (threadIdx.x < D) {
        float ts = s_s[0][threadIdx.x] + s_s[1][threadIdx.x];
        float tq = s_q[0][threadIdx.x] + s_q[1][threadIdx.x];
        atomicAdd(&g_sum[threadIdx.x],   (double)ts);
        atomicAdd(&g_sumsq[threadIdx.x], (double)tq);
    }

    // last block finalizes scale/bias exactly once
    __threadfence();
    __syncthreads();
    __shared__ int s_last;
    if (threadIdx.x == 0)
        s_last = (atomicAdd(&g_done, 1u) == (unsigned)(nblocks - 1));
    __syncthreads();
    if (s_last && threadIdx.x < D) {
        int ch = threadIdx.x;
        double su  = __ldcg(&g_sum[ch]);
        double ssq = __ldcg(&g_sumsq[ch]);
        double mu  = su / (double)N_NODES;
        double var = ssq / (double)N_NODES - mu * mu;
        double rstd = 1.0 / sqrt(var + (double)BN_EPS);
        float sc = gamma[ch] * (float)rstd;
        g_scale[ch] = sc;
        g_bias[ch]  = beta[ch] - (float)mu * sc;
    }
}

// ---------------- K4: BN apply + ReLU (pure memory pass) ----------------
__global__ void __launch_bounds__(256) k_bn(float* __restrict__ out)
{
    __shared__ float4 s_scale4[D / 4];
    __shared__ float4 s_bias4[D / 4];

    int tid = threadIdx.x;
    if (tid < D) {
        ((float*)s_scale4)[tid] = g_scale[tid];
        ((float*)s_bias4)[tid]  = g_bias[tid];
    }
    __syncthreads();

    int i4 = blockIdx.x * blockDim.x + tid;
    if (i4 >= (N_NODES * D) / 4) return;
    int c4 = i4 & (D / 4 - 1);
    float4 sc = s_scale4[c4];
    float4 bi = s_bias4[c4];
    float4 x = ((float4*)out)[i4];
    x.x = fmaxf(fmaf(x.x, sc.x, bi.x), 0.f);
    x.y = fmaxf(fmaf(x.y, sc.y, bi.y), 0.f);
    x.z = fmaxf(fmaf(x.z, sc.z, bi.z), 0.f);
    x.w = fmaxf(fmaf(x.w, sc.w, bi.w), 0.f);
    ((float4*)out)[i4] = x;
}

// ---------------- launch ----------------
extern "C" void kernel_launch(void* const* d_in, const int* in_sizes, int n_in,
                              void* d_out, int out_size)
{
    const float* h     = (const float*)d_in[0];
    const float* norm  = (const float*)d_in[1];
    const float* eps   = (const float*)d_in[2];
    const float* gamma = (const float*)d_in[3];
    const float* beta  = (const float*)d_in[4];
    const int*   src   = (const int*)d_in[5];
    const int*   dst   = (const int*)d_in[6];
    float* out = (float*)d_out;

    (void)in_sizes; (void)n_in; (void)out_size;

    const int total4 = (N_NODES * D) / 4;            // 1.6M float4
    k_init<<<(total4 + 255) / 256, 256>>>(h, norm, eps, out);

    const long long ethreads = (long long)(N_EDGES / 2) * 32;
    k_edges<<<(unsigned)((ethreads + 255) / 256), 256>>>(h, norm, src, dst, out);

    const int sblocks = (N_NODES + SROWS - 1) / SROWS;
    k_stats_partial<<<sblocks, 256>>>(gamma, beta, out, sblocks);

    k_bn<<<(total4 + 255) / 256, 256>>>(out);
}